// round 1
// baseline (speedup 1.0000x reference)
#include <cuda_runtime.h>

// NATTEN 7x7 neighborhood attention, B=2, heads=8, d=32, 56x56, fp32.
// x: (B, 768, 56, 56)  [qkv packed: c = t*256 + head*32 + d]
// rpb: (8, 13, 13)
// out: (B, 256, 56, 56)

#define HH 56
#define WW 56
#define DD 32
#define ROWS 4
#define SROWS 10            // ROWS + 6 halo rows
#define NTHREADS 224        // 56 x 4
#define KVSLICE (SROWS * WW)        // 560 floats per d-slice
#define KVELEMS (DD * KVSLICE)      // 17920 floats per tensor

__global__ __launch_bounds__(NTHREADS, 1)
void natten7x7_kernel(const float* __restrict__ x,
                      const float* __restrict__ rpb,
                      float* __restrict__ out)
{
    extern __shared__ float smem[];
    float* ks = smem;                    // [32][10][56]
    float* vs = smem + KVELEMS;          // [32][10][56]
    float* rs = smem + 2 * KVELEMS;      // [169] rpb for this head

    const int bh   = blockIdx.y;         // 0..15
    const int b    = bh >> 3;
    const int head = bh & 7;
    const int i0   = blockIdx.x * ROWS;
    const int r0   = min(max(i0 - 3, 0), HH - SROWS);

    const int tx = threadIdx.x;          // 0..55 (query col)
    const int ty = threadIdx.y;          // 0..3  (query row in stripe)
    const int tid = ty * WW + tx;

    const float* xb = x + (size_t)b * (768 * HH * WW);
    // k/v global: channel-major planes; 10 full-width rows are contiguous 560 floats
    const float* kg = xb + (size_t)(256 + head * 32) * (HH * WW) + r0 * WW;
    const float* vg = xb + (size_t)(512 + head * 32) * (HH * WW) + r0 * WW;

    // ---- load rpb slice for this head ----
    for (int idx = tid; idx < 169; idx += NTHREADS)
        rs[idx] = rpb[head * 169 + idx];

    // ---- load k/v tile: coalesced global reads, stride-1 smem writes ----
    #pragma unroll 4
    for (int idx = tid; idx < KVELEMS; idx += NTHREADS) {
        const int d  = idx / KVSLICE;
        const int rc = idx - d * KVSLICE;      // r*56 + c within the 10-row band
        const int g  = d * (HH * WW) + rc;
        ks[idx] = kg[g];
        vs[idx] = vg[g];
    }

    // ---- load q (strided over d planes, coalesced over j within a warp) ----
    const int i = i0 + ty;
    const int j = tx;
    const float scale = 0.17677669529663687f;  // 32^-0.5
    float q[DD];
    const float* qg = xb + (size_t)(head * 32) * (HH * WW) + i * WW + j;
    #pragma unroll
    for (int d = 0; d < DD; d++) q[d] = qg[d * (HH * WW)] * scale;

    __syncthreads();

    // window / bias indices (always fully in-bounds after clamping)
    const int ni = min(max(i - 3, 0), HH - 7);
    const int nj = min(max(j - 3, 0), WW - 7);
    const int pi = 6 - (i - ni);
    const int pj = 6 - (j - nj);
    const int wbase = (ni - r0) * WW + nj;   // offset within a d-slice

    // ---- pass 1: logits = qk + bias ----
    float p[49];
    float mx = -1e30f;
    #pragma unroll
    for (int ki = 0; ki < 7; ki++) {
        #pragma unroll
        for (int kj = 0; kj < 7; kj++) {
            const float* kp = ks + wbase + ki * WW + kj;
            float acc0 = rs[(pi + ki) * 13 + (pj + kj)];
            float acc1 = 0.f;
            #pragma unroll
            for (int d = 0; d < DD; d += 2) {
                acc0 += q[d]     * kp[d * KVSLICE];
                acc1 += q[d + 1] * kp[(d + 1) * KVSLICE];
            }
            const float acc = acc0 + acc1;
            p[ki * 7 + kj] = acc;
            mx = fmaxf(mx, acc);
        }
    }

    // ---- softmax (49 entries) ----
    float s = 0.f;
    #pragma unroll
    for (int t = 0; t < 49; t++) {
        p[t] = __expf(p[t] - mx);
        s += p[t];
    }
    const float inv = 1.0f / s;

    // ---- pass 2: weighted sum of v ----
    float o[DD];
    #pragma unroll
    for (int d = 0; d < DD; d++) o[d] = 0.f;
    #pragma unroll
    for (int ki = 0; ki < 7; ki++) {
        #pragma unroll
        for (int kj = 0; kj < 7; kj++) {
            const float w = p[ki * 7 + kj];
            const float* vp = vs + wbase + ki * WW + kj;
            #pragma unroll
            for (int d = 0; d < DD; d++)
                o[d] += w * vp[d * KVSLICE];
        }
    }

    // ---- write out (B, 256, 56, 56) ----
    float* og = out + (size_t)b * (256 * HH * WW)
                    + (size_t)(head * 32) * (HH * WW) + i * WW + j;
    #pragma unroll
    for (int d = 0; d < DD; d++)
        og[d * (HH * WW)] = o[d] * inv;
}

extern "C" void kernel_launch(void* const* d_in, const int* in_sizes, int n_in,
                              void* d_out, int out_size)
{
    const float* x   = (const float*)d_in[0];
    const float* rpb = (const float*)d_in[1];
    float* out = (float*)d_out;

    const int smem_bytes = (2 * KVELEMS + 169) * sizeof(float);  // 144,036 B
    cudaFuncSetAttribute(natten7x7_kernel,
                         cudaFuncAttributeMaxDynamicSharedMemorySize, smem_bytes);

    dim3 grid(HH / ROWS, 2 * 8);   // 14 row-stripes x (B*heads)=16 -> 224 CTAs
    dim3 block(WW, ROWS);          // 56 x 4 = 224 threads
    natten7x7_kernel<<<grid, block, smem_bytes>>>(x, rpb, out);
}

// round 2
// speedup vs baseline: 1.1702x; 1.1702x over previous
#include <cuda_runtime.h>

// NATTEN 7x7 neighborhood attention, B=2, heads=8, d=32, 56x56, fp32.
// x: (B, 768, 56, 56)  [qkv packed: c = t*256 + head*32 + d]
// rpb: (8, 13, 13)
// out: (B, 256, 56, 56)

#define HH 56
#define WW 56
#define DD 32
#define ROWS 8
#define SROWS 14            // ROWS + 6 halo rows
#define NTHREADS 448        // 56 x 8
#define KVSLICE (SROWS * WW)        // 784 floats per d-slice
#define KVELEMS (DD * KVSLICE)      // 25088 floats per tensor
#define PLANE (HH * WW)             // 3136

__global__ __launch_bounds__(NTHREADS, 1)
void natten7x7_kernel(const float* __restrict__ x,
                      const float* __restrict__ rpb,
                      float* __restrict__ out)
{
    extern __shared__ float smem[];
    float* ks = smem;                    // [32][14][56]
    float* vs = smem + KVELEMS;          // [32][14][56]
    float* rs = smem + 2 * KVELEMS;      // [169] rpb for this head

    const int bh   = blockIdx.y;         // 0..15
    const int b    = bh >> 3;
    const int head = bh & 7;
    const int i0   = blockIdx.x * ROWS;
    const int r0   = min(max(i0 - 3, 0), HH - SROWS);

    const int tx = threadIdx.x;          // 0..55 (query col)
    const int ty = threadIdx.y;          // 0..7  (query row in stripe)
    const int tid = ty * WW + tx;

    const float* xb = x + (size_t)b * (768 * PLANE);
    // k/v bands: 14 full-width rows are 784 contiguous floats per d-plane
    const float* kg = xb + (size_t)(256 + head * 32) * PLANE + r0 * WW;
    const float* vg = xb + (size_t)(512 + head * 32) * PLANE + r0 * WW;

    // ---- load rpb slice for this head ----
    if (tid < 169) rs[tid] = rpb[head * 169 + tid];

    // ---- load k/v tile with float4 (band start is 16B-aligned: r0*56 % 4 == 0) ----
    {
        const float4* kg4 = (const float4*)kg;
        const float4* vg4 = (const float4*)vg;
        float4* ks4 = (float4*)ks;
        float4* vs4 = (float4*)vs;
        const int NV4 = KVELEMS / 4;            // 6272
        #pragma unroll
        for (int idx = tid; idx < NV4; idx += NTHREADS) {
            const int d  = idx / (KVSLICE / 4);          // KVSLICE/4 = 196
            const int rc = idx - d * (KVSLICE / 4);
            const int g  = d * (PLANE / 4) + rc;         // PLANE/4 = 784
            ks4[idx] = kg4[g];
            vs4[idx] = vg4[g];
        }
    }

    // ---- load q (coalesced over j within each warp) ----
    const int i = i0 + ty;
    const int j = tx;
    const float scale = 0.17677669529663687f;  // 32^-0.5
    float q[DD];
    const float* qg = xb + (size_t)(head * 32) * PLANE + i * WW + j;
    #pragma unroll
    for (int d = 0; d < DD; d++) q[d] = qg[d * PLANE] * scale;

    __syncthreads();

    // window / bias indices (fully in-bounds after clamping; L=56 >= K=7)
    const int ni = min(max(i - 3, 0), HH - 7);
    const int nj = min(max(j - 3, 0), WW - 7);
    const int pi = 6 - (i - ni);
    const int pj = 6 - (j - nj);
    const int wbase = (ni - r0) * WW + nj;   // offset within a d-slice

    // ---- pass 1: logits = qk + bias ----
    float p[49];
    float mx = -1e30f;
    #pragma unroll
    for (int ki = 0; ki < 7; ki++) {
        #pragma unroll
        for (int kj = 0; kj < 7; kj++) {
            const float* kp = ks + wbase + ki * WW + kj;
            float acc0 = rs[(pi + ki) * 13 + (pj + kj)];
            float acc1 = 0.f;
            #pragma unroll
            for (int d = 0; d < DD; d += 2) {
                acc0 += q[d]     * kp[d * KVSLICE];
                acc1 += q[d + 1] * kp[(d + 1) * KVSLICE];
            }
            const float acc = acc0 + acc1;
            p[ki * 7 + kj] = acc;
            mx = fmaxf(mx, acc);
        }
    }

    // ---- softmax (49 entries) ----
    float s = 0.f;
    #pragma unroll
    for (int t = 0; t < 49; t++) {
        p[t] = __expf(p[t] - mx);
        s += p[t];
    }
    const float inv = 1.0f / s;

    // ---- pass 2: weighted sum of v ----
    float o[DD];
    #pragma unroll
    for (int d = 0; d < DD; d++) o[d] = 0.f;
    #pragma unroll
    for (int ki = 0; ki < 7; ki++) {
        #pragma unroll
        for (int kj = 0; kj < 7; kj++) {
            const float w = p[ki * 7 + kj];
            const float* vp = vs + wbase + ki * WW + kj;
            #pragma unroll
            for (int d = 0; d < DD; d++)
                o[d] += w * vp[d * KVSLICE];
        }
    }

    // ---- write out (B, 256, 56, 56) ----
    float* og = out + (size_t)b * (256 * PLANE)
                    + (size_t)(head * 32) * PLANE + i * WW + j;
    #pragma unroll
    for (int d = 0; d < DD; d++)
        og[d * PLANE] = o[d] * inv;
}

extern "C" void kernel_launch(void* const* d_in, const int* in_sizes, int n_in,
                              void* d_out, int out_size)
{
    const float* x   = (const float*)d_in[0];
    const float* rpb = (const float*)d_in[1];
    float* out = (float*)d_out;

    const int smem_bytes = (2 * KVELEMS + 169) * sizeof(float);  // 201,380 B
    cudaFuncSetAttribute(natten7x7_kernel,
                         cudaFuncAttributeMaxDynamicSharedMemorySize, smem_bytes);

    dim3 grid(HH / ROWS, 2 * 8);   // 7 row-stripes x (B*heads)=16 -> 112 CTAs (single wave)
    dim3 block(WW, ROWS);          // 56 x 8 = 448 threads
    natten7x7_kernel<<<grid, block, smem_bytes>>>(x, rpb, out);
}

// round 4
// speedup vs baseline: 1.7945x; 1.5334x over previous
#include <cuda_runtime.h>
#include <cstdint>

// NATTEN 7x7, B=2, heads=8, d=32, 56x56, fp32.
// x: (B,768,56,56) qkv-packed; rpb: (8,13,13); out: (B,256,56,56).

#define HH 56
#define WW 56
#define PLANE 3136
#define ROWS 8
#define SROWS 14
#define NT 224               // 56 x 4 threads, 2 query rows per thread
#define CS 36                // padded d-stride (floats) per (row,col) slot
#define TSLOTS (SROWS * WW)  // 784 slots
#define TELEMS (TSLOTS * CS) // 28224 floats per tensor

__device__ __forceinline__ uint64_t pack2(float lo, float hi) {
    uint64_t r; asm("mov.b64 %0, {%1,%2};" : "=l"(r) : "f"(lo), "f"(hi)); return r;
}
__device__ __forceinline__ float2 unpack2(uint64_t v) {
    float2 f; asm("mov.b64 {%0,%1}, %2;" : "=f"(f.x), "=f"(f.y) : "l"(v)); return f;
}
__device__ __forceinline__ uint64_t ffma2(uint64_t a, uint64_t b, uint64_t c) {
    uint64_t d; asm("fma.rn.f32x2 %0, %1, %2, %3;" : "=l"(d) : "l"(a), "l"(b), "l"(c)); return d;
}
__device__ __forceinline__ uint64_t fadd2(uint64_t a, uint64_t b) {
    uint64_t d; asm("add.rn.f32x2 %0, %1, %2;" : "=l"(d) : "l"(a), "l"(b)); return d;
}
__device__ __forceinline__ void lds16(uint32_t a, uint64_t& x, uint64_t& y) {
    asm volatile("ld.shared.v2.b64 {%0,%1}, [%2];" : "=l"(x), "=l"(y) : "r"(a));
}

__global__ __launch_bounds__(NT, 1)
void natten7x7_kernel(const float* __restrict__ x,
                      const float* __restrict__ rpb,
                      float* __restrict__ out)
{
    extern __shared__ float smem[];
    float* ks = smem;                 // [784][36]
    float* vs = smem + TELEMS;        // [784][36]
    float* rs = smem + 2 * TELEMS;    // [169] (+pad; guarded-OOB bias indices stay in alloc)

    const int bh = blockIdx.y, b = bh >> 3, head = bh & 7;
    const int i0 = blockIdx.x * ROWS;
    const int r0 = min(max(i0 - 3, 0), HH - SROWS);

    const int tx = threadIdx.x, ty = threadIdx.y;
    const int tid = ty * WW + tx;

    const float* xb = x + (size_t)b * (768 * PLANE);
    const float* kg = xb + (size_t)(256 + head * 32) * PLANE + r0 * WW;
    const float* vg = xb + (size_t)(512 + head * 32) * PLANE + r0 * WW;

    if (tid < 169) rs[tid] = rpb[head * 169 + tid];

    // ---- transpose-load K/V: gmem (d-major planes) -> smem [slot][d], STS.128 along d ----
    #pragma unroll 4
    for (int it = 0; it < 56; it++) {
        const int idx  = it * NT + tid;
        const int tsel = idx >= (8 * TSLOTS);
        const int rem  = idx - tsel * (8 * TSLOTS);
        const int dblk = rem / TSLOTS;
        const int rc   = rem - dblk * TSLOTS;
        const float* g = (tsel ? vg : kg) + dblk * 4 * PLANE + rc;
        float4 v4 = make_float4(g[0], g[PLANE], g[2 * PLANE], g[3 * PLANE]);
        *(float4*)((tsel ? vs : ks) + rc * CS + dblk * 4) = v4;
    }

    // ---- load + pack q for both rows ----
    const int iA = i0 + 2 * ty, iB = iA + 1, j = tx;
    const float scale = 0.17677669529663687f;  // 32^-0.5
    uint64_t qA[16], qB[16];
    {
        const float* qa = xb + (size_t)(head * 32) * PLANE + iA * WW + j;
        const float* qb = qa + WW;
        #pragma unroll
        for (int t = 0; t < 16; t++) {
            qA[t] = pack2(qa[(2 * t) * PLANE] * scale, qa[(2 * t + 1) * PLANE] * scale);
            qB[t] = pack2(qb[(2 * t) * PLANE] * scale, qb[(2 * t + 1) * PLANE] * scale);
        }
    }
    __syncthreads();

    // ---- window geometry (union of two 7-row windows = 8 rows, off in {0,1}) ----
    const int niA = min(max(iA - 3, 0), HH - 7);
    const int niB = min(max(iB - 3, 0), HH - 7);
    const int off = niB - niA;
    const int piA = 6 - (iA - niA);
    const int piB = 6 - (iB - niB);
    const int nj  = min(max(j - 3, 0), WW - 7);
    const int pj  = 6 - (j - nj);
    const int rbase = niA - r0;   // 0..7 (7 only in edge stripes, where off==0)

    const uint32_t sbase = (uint32_t)__cvta_generic_to_shared(ks) + (uint32_t)(nj * CS * 4);

    // Per-rr tile row, clamped in-bounds. When rbase+rr > 13 the row is fully
    // masked for both queries (rbase==7 implies off==0), so the clamped read's
    // finite garbage is multiplied by an exact 0 weight.
    int srow[8];
    #pragma unroll
    for (int rr = 0; rr < 8; rr++) srow[rr] = min(rbase + rr, SROWS - 1);

    // ---- pass 1: logits (shared K reads feed both queries) ----
    float pA[49], pB[56];
    float mxA = -1e30f, mxB = -1e30f;
    #pragma unroll
    for (int rr = 0; rr < 8; rr++) {
        const bool vB = off ? (rr >= 1) : (rr <= 6);
        #pragma unroll
        for (int kj = 0; kj < 7; kj++) {
            const uint32_t a = sbase + (uint32_t)((srow[rr] * WW + kj) * CS * 4);
            uint64_t kt[16];
            #pragma unroll
            for (int u = 0; u < 8; u++) lds16(a + 16 * u, kt[2 * u], kt[2 * u + 1]);

            if (rr < 7) {
                uint64_t a0 = ffma2(qA[0], kt[0], 0ull);
                uint64_t a1 = ffma2(qA[1], kt[1], 0ull);
                #pragma unroll
                for (int t = 2; t < 16; t += 2) {
                    a0 = ffma2(qA[t],     kt[t],     a0);
                    a1 = ffma2(qA[t + 1], kt[t + 1], a1);
                }
                float2 f = unpack2(fadd2(a0, a1));
                const float logit = f.x + f.y + rs[(piA + rr) * 13 + pj + kj];
                pA[rr * 7 + kj] = logit;
                mxA = fmaxf(mxA, logit);
            }
            {
                uint64_t b0 = ffma2(qB[0], kt[0], 0ull);
                uint64_t b1 = ffma2(qB[1], kt[1], 0ull);
                #pragma unroll
                for (int t = 2; t < 16; t += 2) {
                    b0 = ffma2(qB[t],     kt[t],     b0);
                    b1 = ffma2(qB[t + 1], kt[t + 1], b1);
                }
                float2 f = unpack2(fadd2(b0, b1));
                const float bias = vB ? rs[(piB + rr - off) * 13 + pj + kj] : -1e30f;
                const float logit = f.x + f.y + bias;
                pB[rr * 7 + kj] = logit;
                mxB = fmaxf(mxB, logit);
            }
        }
    }

    // ---- softmax (unnormalized; fold 1/sum into output) ----
    float sA = 0.f, sB = 0.f;
    #pragma unroll
    for (int t = 0; t < 49; t++) { pA[t] = __expf(pA[t] - mxA); sA += pA[t]; }
    #pragma unroll
    for (int t = 0; t < 56; t++) { pB[t] = __expf(pB[t] - mxB); sB += pB[t]; }
    const float invA = 1.0f / sA, invB = 1.0f / sB;

    // ---- pass 2: AV (shared V reads feed both queries) ----
    const uint32_t vbase = sbase + (uint32_t)(TELEMS * 4);
    uint64_t oA[16], oB[16];
    #pragma unroll
    for (int t = 0; t < 16; t++) { oA[t] = 0ull; oB[t] = 0ull; }
    #pragma unroll
    for (int rr = 0; rr < 8; rr++) {
        #pragma unroll
        for (int kj = 0; kj < 7; kj++) {
            const uint32_t a = vbase + (uint32_t)((srow[rr] * WW + kj) * CS * 4);
            uint64_t vt[16];
            #pragma unroll
            for (int u = 0; u < 8; u++) lds16(a + 16 * u, vt[2 * u], vt[2 * u + 1]);

            if (rr < 7) {
                const float w = pA[rr * 7 + kj];
                const uint64_t w2 = pack2(w, w);
                #pragma unroll
                for (int t = 0; t < 16; t++) oA[t] = ffma2(w2, vt[t], oA[t]);
            }
            {
                const float w = pB[rr * 7 + kj];   // masked entries are exactly 0
                const uint64_t w2 = pack2(w, w);
                #pragma unroll
                for (int t = 0; t < 16; t++) oB[t] = ffma2(w2, vt[t], oB[t]);
            }
        }
    }

    // ---- write out (B,256,56,56) ----
    float* oga = out + (size_t)b * (256 * PLANE) + (size_t)(head * 32) * PLANE + iA * WW + j;
    float* ogb = oga + WW;
    #pragma unroll
    for (int t = 0; t < 16; t++) {
        float2 fa = unpack2(oA[t]);
        float2 fb = unpack2(oB[t]);
        oga[(2 * t) * PLANE]     = fa.x * invA;
        oga[(2 * t + 1) * PLANE] = fa.y * invA;
        ogb[(2 * t) * PLANE]     = fb.x * invB;
        ogb[(2 * t + 1) * PLANE] = fb.y * invB;
    }
}

extern "C" void kernel_launch(void* const* d_in, const int* in_sizes, int n_in,
                              void* d_out, int out_size)
{
    const float* x   = (const float*)d_in[0];
    const float* rpb = (const float*)d_in[1];
    float* out = (float*)d_out;

    const int smem_bytes = (2 * TELEMS + 192) * sizeof(float);  // 226,560 B
    cudaFuncSetAttribute(natten7x7_kernel,
                         cudaFuncAttributeMaxDynamicSharedMemorySize, smem_bytes);

    dim3 grid(HH / ROWS, 2 * 8);   // 7 x 16 = 112 CTAs -> single wave
    dim3 block(WW, 4);             // 224 threads, each owns 2 query rows
    natten7x7_kernel<<<grid, block, smem_bytes>>>(x, rpb, out);
}